// round 5
// baseline (speedup 1.0000x reference)
#include <cuda_runtime.h>
#include <cuda_bf16.h>
#include <cstdint>

// Problem constants (fixed by setup_inputs)
#define BB 4
#define CC 128
#define HH 512
#define WW 512
#define HWPX (HH * WW)          // 262144 pixels per image
#define NT 800                  // n_tokens
#define ML 1024                 // max_length
#define NSEG (BB * NT)          // 3200
#define NCLS 5

// Output layout (concatenated f32): tokens [B,ML,C] | labels [B,ML] | pads [B,1]
#define TOK_ELEMS ((size_t)BB * ML * CC)   // 524288
#define LAB_OFF   TOK_ELEMS
#define PAD_OFF   (TOK_ELEMS + (size_t)BB * ML)

// Global accumulator, layout [half][image][800][64]  (= NSEG*CC floats, 1.6MB)
__device__ __align__(1024) float g_accum[NSEG * CC];
__device__ int g_hist[NSEG * NCLS];

// ---------------------------------------------------------------------------
// K1: zero accumulators + histograms
// ---------------------------------------------------------------------------
__global__ void k1_init() {
    int i = blockIdx.x * blockDim.x + threadIdx.x;
    if (i < NSEG * CC) g_accum[i] = 0.f;
    if (i < NSEG * NCLS) g_hist[i] = 0;
}

// ---------------------------------------------------------------------------
// Main pass: one channel-half (64 ch) of one image per CTA-row.
// Grid (37, 4): 148 CTAs = one full wave, 1 CTA/SM (217 KB smem).
// CTA keeps a PRIVATE smem accumulator acc[800][64] (200 KB) -> all the
// segment-reduction RMW happens in smem (conflict-free ATOMS, bank = lane),
// L2 only sees the 512 MB fill read + a single 200 KB TMA-reduce flush.
//  - subtile = 32 px x 64 ch, double-buffered, 1 __syncthreads per subtile
//  - stage1 STS bank (c+l)%32 conflict-free; stage2 LDS bank (l+p)%32
//    conflict-free; smem atomicAdd bank = l conflict-free.
// ---------------------------------------------------------------------------
#define ACC_FLOATS (NT * 64)            // 51200
#define TILE_FLOATS (64 * 33)           // 2112
#define SMEM_BYTES ((ACC_FLOATS + 2 * TILE_FLOATS + 64) * 4)

__global__ __launch_bounds__(512) void k_pass(const float* __restrict__ F,
                                              const int* __restrict__ seg,
                                              const int* __restrict__ gts,
                                              int h) {
    extern __shared__ float smem[];
    float* acc   = smem;                        // [800][64]
    float* tileA = acc + ACC_FLOATS;            // [64][33]
    float* tileB = tileA + TILE_FLOATS;
    int*   ssegA = (int*)(tileB + TILE_FLOATS); // [32]
    int*   ssegB = ssegA + 32;

    int b   = blockIdx.y;
    int cta = blockIdx.x;                       // 0..36
    int t   = threadIdx.x;
    int w   = t >> 5;
    int l   = t & 31;

    for (int i = t; i < ACC_FLOATS; i += 512) acc[i] = 0.f;

    const float* Fb   = F + ((size_t)b * CC + (size_t)h * 64) * HWPX;
    const int*   segb = seg + (size_t)b * HWPX;
    const int*   gtsb = gts + (size_t)b * HWPX;

    // ---- subtile loader ----
    auto load_st = [&](int st, float* tile, int* ss) {
        int p0 = st << 5;
        if (t < 32) {
            int s = segb[p0 + t];
            ss[t] = s;
            if (h == 0)
                atomicAdd(&g_hist[(s + b * NT) * NCLS + gtsb[p0 + t]], 1);
        }
#pragma unroll
        for (int k = 0; k < 4; k++) {
            int c = (k << 4) + w;               // 16 warps cover 64 channels
            tile[c * 33 + l] = Fb[(size_t)c * HWPX + p0 + l];
        }
    };
    // ---- subtile accumulator ----
    auto accum_st = [&](const float* tile, const int* ss) {
#pragma unroll
        for (int i = 0; i < 2; i++) {
            int p = (w << 1) + i;               // 16 warps x 2 = 32 pixels
            int s = ss[p];
            float v0 = tile[l * 33 + p];
            float v1 = tile[(l + 32) * 33 + p];
            atomicAdd(&acc[s * 64 + l], v0);
            atomicAdd(&acc[s * 64 + l + 32], v1);
        }
    };

    // ---- software-pipelined loop over this CTA's subtiles ----
    int st = cta;                               // 8192 subtiles per image
    load_st(st, tileA, ssegA);
    __syncthreads();
    bool cur = 0;
    for (int nxt = st + 37; nxt < 8192; nxt += 37) {
        if (!cur) { load_st(nxt, tileB, ssegB); accum_st(tileA, ssegA); }
        else      { load_st(nxt, tileA, ssegA); accum_st(tileB, ssegB); }
        __syncthreads();
        cur = !cur;
    }
    if (!cur) accum_st(tileA, ssegA); else accum_st(tileB, ssegB);
    __syncthreads();

    // ---- flush: TMA bulk-reduce the private accumulator into g_accum ----
    asm volatile("fence.proxy.async.shared::cta;" ::: "memory");
    if (l == 0) {
        // warp w owns 3200 floats (12800 B), flushed as 4 x 3200 B ops
        size_t base = ((size_t)(h * BB + b) * NT) * 64 + (size_t)w * 3200;
#pragma unroll
        for (int q = 0; q < 4; q++) {
            float* dst = g_accum + base + q * 800;
            uint32_t src = (uint32_t)__cvta_generic_to_shared(acc + w * 3200 + q * 800);
            asm volatile(
                "cp.reduce.async.bulk.global.shared::cta.bulk_group.add.f32 "
                "[%0], [%1], %2;"
                :: "l"(dst), "r"(src), "r"(3200) : "memory");
        }
        asm volatile("cp.async.bulk.commit_group;" ::: "memory");
        asm volatile("cp.async.bulk.wait_group 0;" ::: "memory");
    }
}

// ---------------------------------------------------------------------------
// K4: finalize. Block per (b, sl): mean, mode, padding, pads.
// g_accum layout [h][b][sl][c] -> output position t = h*64+c (natural order).
// ---------------------------------------------------------------------------
__global__ __launch_bounds__(128) void k4_final(float* __restrict__ out) {
    int b  = blockIdx.y;
    int sl = blockIdx.x;
    int t  = threadIdx.x;

    float* tok = out + ((size_t)b * ML + sl) * CC;

    if (sl >= NT) {                       // padding region
        tok[t] = 0.f;
        if (t == 0) out[LAB_OFF + (size_t)b * ML + sl] = 0.f;
        return;
    }

    int s = b * NT + sl;

    __shared__ int s_cnt;
    if (t == 0) {
        int h[NCLS], cnt = 0;
#pragma unroll
        for (int c = 0; c < NCLS; c++) { h[c] = g_hist[s * NCLS + c]; cnt += h[c]; }
        int best = 0, bc = h[0];
#pragma unroll
        for (int c = 1; c < NCLS; c++) if (h[c] > bc) { bc = h[c]; best = c; }
        out[LAB_OFF + (size_t)b * ML + sl] = (float)best;
        if (sl == 0) out[PAD_OFF + b] = (float)(ML - NT);
        s_cnt = cnt;
    }
    __syncthreads();

    int cnt = s_cnt;
    float inv = 1.f / (float)(cnt > 0 ? cnt : 1);
    int hh = t >> 6, c = t & 63;
    float v = g_accum[(((size_t)(hh * BB + b) * NT) + sl) * 64 + c];
    tok[t] = v * inv;
}

// ---------------------------------------------------------------------------
extern "C" void kernel_launch(void* const* d_in, const int* in_sizes, int n_in,
                              void* d_out, int out_size) {
    const float* features = (const float*)d_in[0];
    const int*   gts      = (const int*)d_in[1];
    const int*   segments = (const int*)d_in[2];
    float*       out      = (float*)d_out;

    (void)in_sizes; (void)n_in; (void)out_size;

    static bool attr_set = false;
    if (!attr_set) {
        cudaFuncSetAttribute(k_pass, cudaFuncAttributeMaxDynamicSharedMemorySize,
                             SMEM_BYTES);
        attr_set = true;
    }

    k1_init<<<(NSEG * CC + 255) / 256, 256>>>();
    {
        dim3 g(37, BB);                    // 148 CTAs = one wave
        k_pass<<<g, 512, SMEM_BYTES>>>(features, segments, gts, 0);
        k_pass<<<g, 512, SMEM_BYTES>>>(features, segments, gts, 1);
    }
    {
        dim3 g(ML, BB);                    // (1024, 4)
        k4_final<<<g, 128>>>(out);
    }
}

// round 6
// speedup vs baseline: 1.7378x; 1.7378x over previous
#include <cuda_runtime.h>
#include <cuda_bf16.h>
#include <cstdint>

// Problem constants (fixed by setup_inputs)
#define BB 4
#define CC 128
#define HH 512
#define WW 512
#define HWPX (HH * WW)          // 262144 pixels per image
#define NT 800                  // n_tokens
#define ML 1024                 // max_length
#define NSEG (BB * NT)          // 3200
#define NCLS 5

// Output layout (concatenated f32): tokens [B,ML,C] | labels [B,ML] | pads [B,1]
#define TOK_ELEMS ((size_t)BB * ML * CC)   // 524288
#define LAB_OFF   TOK_ELEMS
#define PAD_OFF   (TOK_ELEMS + (size_t)BB * ML)

// Global accumulator, layout [half][image][800][64]  (NSEG*CC floats, 1.6MB)
__device__ __align__(1024) float g_accum[NSEG * CC];
__device__ int g_hist[NSEG * NCLS];

// ---------------------------------------------------------------------------
// K1: zero accumulators + histograms
// ---------------------------------------------------------------------------
__global__ void k1_init() {
    int i = blockIdx.x * blockDim.x + threadIdx.x;
    if (i < NSEG * CC) g_accum[i] = 0.f;
    if (i < NSEG * NCLS) g_hist[i] = 0;
}

// ---------------------------------------------------------------------------
// Main pass: one channel-half (64 ch) of one image per CTA-row.
// Grid (37, 4) = 148 CTAs = one wave, 1 CTA/SM, 512 threads (16 warps).
// CTA-private smem accumulator acc[800][64] (200 KB). NO atomics:
// warp w exclusively owns segments with (s & 15) == w. Per 32-px subtile,
// each warp ballots which pixels it owns and accumulates their channel
// columns straight from the [c][p] pitch-33 tile:
//   tile LDS  bank = (33c + p) % 32 = (c + p) % 32, c = l / l+32 -> dense ✓
//   acc  LDS/STS bank = (64s + l) % 32 = l ✓
// Double-buffered tiles, register prefetch, one barrier per round.
// End: single 200 KB TMA bulk-reduce flush into g_accum (L2-resident).
// ---------------------------------------------------------------------------
#define ACC_FLOATS (NT * 64)            // 51200
#define TILE_FLOATS (64 * 33)           // 2112
#define SMEM_FLOATS (ACC_FLOATS + 2 * TILE_FLOATS + 64)
#define SMEM_BYTES (SMEM_FLOATS * 4)    // ~217 KB

__global__ __launch_bounds__(512) void k_pass(const float* __restrict__ F,
                                              const int* __restrict__ seg,
                                              const int* __restrict__ gts,
                                              int h) {
    extern __shared__ float smem[];
    float* acc  = smem;                         // [800][64]
    float* tile0 = acc + ACC_FLOATS;            // [64][33]
    float* tile1 = tile0 + TILE_FLOATS;
    int*   sseg0 = (int*)(tile1 + TILE_FLOATS); // [32]
    int*   sseg1 = sseg0 + 32;

    int b   = blockIdx.y;
    int cta = blockIdx.x;                       // 0..36
    int t   = threadIdx.x;
    int w   = t >> 5;
    int l   = t & 31;

    for (int i = t; i < ACC_FLOATS; i += 512) acc[i] = 0.f;

    const float* Fb   = F + ((size_t)b * CC + (size_t)h * 64) * HWPX;
    const int*   segb = seg + (size_t)b * HWPX;
    const int*   gtsb = gts + (size_t)b * HWPX;

    float r[4];                                 // prefetch registers
    int   rseg = 0;

    // LDG issue for subtile st (no smem writes)
    auto prefetch = [&](int st) {
        int p0 = st << 5;
        if (t < 32) {
            rseg = segb[p0 + t];
            if (h == 0)
                atomicAdd(&g_hist[(rseg + b * NT) * NCLS + gtsb[p0 + t]], 1);
        }
#pragma unroll
        for (int k = 0; k < 4; k++) {
            int c = (k << 4) + w;               // 16 warps cover 64 channels
            r[k] = Fb[(size_t)c * HWPX + p0 + l];
        }
    };
    // drain registers into a tile buffer
    auto store_t = [&](float* tile, int* ss) {
        if (t < 32) ss[t] = rseg;
#pragma unroll
        for (int k = 0; k < 4; k++) {
            int c = (k << 4) + w;
            tile[c * 33 + l] = r[k];            // bank (c+l)%32 ✓
        }
    };
    // warp-ownership combine (no atomics)
    auto accum_t = [&](const float* tile, const int* ss) {
        int myseg = ss[l];                      // 1 LDS, conflict-free
        unsigned mask = __ballot_sync(0xffffffffu, (myseg & 15) == w);
        while (mask) {
            int p = __ffs(mask) - 1;
            mask &= mask - 1;
            int s = __shfl_sync(0xffffffffu, myseg, p);
            float v0 = tile[l * 33 + p];        // bank (l+p)%32 ✓
            float v1 = tile[(l + 32) * 33 + p];
            acc[s * 64 + l]      += v0;         // bank l ✓, exclusive owner
            acc[s * 64 + l + 32] += v1;
        }
    };

    // rounds: subtiles st = cta + 37*k
    prefetch(cta);
    int st = cta;
    while (true) {
        float* tile = (st / 37 & 1) ? tile1 : tile0;
        int*   ss   = (st / 37 & 1) ? sseg1 : sseg0;
        store_t(tile, ss);
        __syncthreads();
        int nxt = st + 37;
        if (nxt < 8192) prefetch(nxt);          // LDG overlaps combine below
        accum_t(tile, ss);
        if (nxt >= 8192) break;
        st = nxt;
    }
    __syncthreads();

    // ---- flush: TMA bulk-reduce the private accumulator into g_accum ----
    asm volatile("fence.proxy.async.shared::cta;" ::: "memory");
    if (l == 0) {
        size_t base = ((size_t)(h * BB + b) * NT) * 64 + (size_t)w * 3200;
#pragma unroll
        for (int q = 0; q < 4; q++) {
            float* dst = g_accum + base + q * 800;
            uint32_t src = (uint32_t)__cvta_generic_to_shared(acc + w * 3200 + q * 800);
            asm volatile(
                "cp.reduce.async.bulk.global.shared::cta.bulk_group.add.f32 "
                "[%0], [%1], %2;"
                :: "l"(dst), "r"(src), "r"(3200) : "memory");
        }
        asm volatile("cp.async.bulk.commit_group;" ::: "memory");
        asm volatile("cp.async.bulk.wait_group 0;" ::: "memory");
    }
}

// ---------------------------------------------------------------------------
// K4: finalize. Block per (b, sl): mean, mode, padding, pads.
// g_accum layout [h][b][sl][c] -> output position t = h*64+c (natural order).
// ---------------------------------------------------------------------------
__global__ __launch_bounds__(128) void k4_final(float* __restrict__ out) {
    int b  = blockIdx.y;
    int sl = blockIdx.x;
    int t  = threadIdx.x;

    float* tok = out + ((size_t)b * ML + sl) * CC;

    if (sl >= NT) {                       // padding region
        tok[t] = 0.f;
        if (t == 0) out[LAB_OFF + (size_t)b * ML + sl] = 0.f;
        return;
    }

    int s = b * NT + sl;

    __shared__ int s_cnt;
    if (t == 0) {
        int hh[NCLS], cnt = 0;
#pragma unroll
        for (int c = 0; c < NCLS; c++) { hh[c] = g_hist[s * NCLS + c]; cnt += hh[c]; }
        int best = 0, bc = hh[0];
#pragma unroll
        for (int c = 1; c < NCLS; c++) if (hh[c] > bc) { bc = hh[c]; best = c; }
        out[LAB_OFF + (size_t)b * ML + sl] = (float)best;
        if (sl == 0) out[PAD_OFF + b] = (float)(ML - NT);
        s_cnt = cnt;
    }
    __syncthreads();

    int cnt = s_cnt;
    float inv = 1.f / (float)(cnt > 0 ? cnt : 1);
    int hh = t >> 6, c = t & 63;
    float v = g_accum[(((size_t)(hh * BB + b) * NT) + sl) * 64 + c];
    tok[t] = v * inv;
}

// ---------------------------------------------------------------------------
extern "C" void kernel_launch(void* const* d_in, const int* in_sizes, int n_in,
                              void* d_out, int out_size) {
    const float* features = (const float*)d_in[0];
    const int*   gts      = (const int*)d_in[1];
    const int*   segments = (const int*)d_in[2];
    float*       out      = (float*)d_out;

    (void)in_sizes; (void)n_in; (void)out_size;

    static bool attr_set = false;
    if (!attr_set) {
        cudaFuncSetAttribute(k_pass, cudaFuncAttributeMaxDynamicSharedMemorySize,
                             SMEM_BYTES);
        attr_set = true;
    }

    k1_init<<<(NSEG * CC + 255) / 256, 256>>>();
    {
        dim3 g(37, BB);                    // 148 CTAs = one wave
        k_pass<<<g, 512, SMEM_BYTES>>>(features, segments, gts, 0);
        k_pass<<<g, 512, SMEM_BYTES>>>(features, segments, gts, 1);
    }
    {
        dim3 g(ML, BB);                    // (1024, 4)
        k4_final<<<g, 128>>>(out);
    }
}

// round 9
// speedup vs baseline: 2.5294x; 1.4555x over previous
#include <cuda_runtime.h>
#include <cuda_bf16.h>
#include <cstdint>

// Problem constants (fixed by setup_inputs)
#define BB 4
#define CC 128
#define HH 512
#define WW 512
#define HWPX (HH * WW)          // 262144 pixels per image
#define NT 800                  // n_tokens
#define ML 1024                 // max_length
#define NSEG (BB * NT)          // 3200
#define NCLS 5

// Output layout (concatenated f32): tokens [B,ML,C] | labels [B,ML] | pads [B,1]
#define TOK_ELEMS ((size_t)BB * ML * CC)   // 524288
#define LAB_OFF   TOK_ELEMS
#define PAD_OFF   (TOK_ELEMS + (size_t)BB * ML)

// Global accumulator, layout [half][image][800][64]  (NSEG*CC floats, 1.6MB)
__device__ __align__(1024) float g_accum[NSEG * CC];
__device__ int g_hist[NSEG * NCLS];

// ---------------------------------------------------------------------------
// K1: zero accumulators + histograms
// ---------------------------------------------------------------------------
__global__ void k1_init() {
    int i = blockIdx.x * blockDim.x + threadIdx.x;
    if (i < NSEG * CC) g_accum[i] = 0.f;
    if (i < NSEG * NCLS) g_hist[i] = 0;
}

// ---------------------------------------------------------------------------
// Main pass: grid (37, B, 2); z = channel half. 296 CTAs = 2 clean waves,
// 1 CTA/SM (226 KB smem), 512 threads (16 warps).
// CTA-private smem accumulator acc[800][64]. No data atomics:
// warp w exclusively owns segments with (s & 15) == w (ballot+shfl combine).
// 3-deep cp.async pipeline: subtile = 32 px x 64 ch loaded via LDGSTS.32
// into pitch-33 tiles; one commit_group per round (empty commits in the
// tail keep wait_group 2 exact). Lookahead 2 rounds hides DRAM latency.
//   tile STS (cp.async): warp-contiguous -> conflict-free
//   tile LDS: bank (l+p)%32 -> conflict-free
//   acc LDS/STS: bank l -> conflict-free, exclusive owner
// End: per-warp 12800B TMA bulk-reduce flush into L2-resident g_accum.
// ---------------------------------------------------------------------------
#define ACC_FLOATS (NT * 64)            // 51200
#define TILE_FLOATS (64 * 33)           // 2112
#define NBUF 3
#define SMEM_BYTES ((ACC_FLOATS + NBUF * TILE_FLOATS) * 4 + NBUF * 32 * 8)

#define CP4(dst, src)                                                        \
    asm volatile("cp.async.ca.shared.global [%0], [%1], 4;"                  \
                 :: "r"((uint32_t)__cvta_generic_to_shared(dst)),            \
                    "l"(src) : "memory")

__global__ __launch_bounds__(512) void k_pass(const float* __restrict__ F,
                                              const int* __restrict__ seg,
                                              const int* __restrict__ gts) {
    extern __shared__ float smem[];
    float* acc     = smem;                               // [800][64]
    float* tilebuf = acc + ACC_FLOATS;                   // 3 x [64][33]
    int*   sseg    = (int*)(tilebuf + NBUF * TILE_FLOATS);  // 3 x [32]
    int*   sgts    = sseg + NBUF * 32;                       // 3 x [32]

    int b   = blockIdx.y;
    int h   = blockIdx.z;
    int cta = blockIdx.x;                       // 0..36
    int t   = threadIdx.x;
    int w   = t >> 5;
    int l   = t & 31;

    for (int i = t; i < ACC_FLOATS; i += 512) acc[i] = 0.f;
    __syncthreads();

    const float* Fb   = F + ((size_t)b * CC + (size_t)h * 64) * HWPX;
    const int*   segb = seg + (size_t)b * HWPX;
    const int*   gtsb = gts + (size_t)b * HWPX;

    // issue subtile st into buffer buf (or just an empty commit)
    auto issue = [&](int st, int buf) {
        if (st < 8192) {
            int p0 = st << 5;
            float* tile = tilebuf + buf * TILE_FLOATS;
            if (t < 32) {
                CP4(&sseg[buf * 32 + t], segb + p0 + t);
                CP4(&sgts[buf * 32 + t], gtsb + p0 + t);
            }
#pragma unroll
            for (int k = 0; k < 4; k++) {
                int c = (k << 4) + w;               // 16 warps cover 64 ch
                CP4(&tile[c * 33 + l], Fb + (size_t)c * HWPX + p0 + l);
            }
        }
        asm volatile("cp.async.commit_group;" ::: "memory");
    };

    // combine buffer buf into the private accumulator (no atomics)
    auto accum = [&](int buf) {
        const float* tile = tilebuf + buf * TILE_FLOATS;
        const int*   ss   = sseg + buf * 32;
        int myseg = ss[l];                          // conflict-free LDS
        if (w == 15 && h == 0)                      // hist on warp 15
            atomicAdd(&g_hist[(myseg + b * NT) * NCLS + sgts[buf * 32 + l]], 1);
        unsigned mask = __ballot_sync(0xffffffffu, (myseg & 15) == w);
        while (mask) {
            int p = __ffs(mask) - 1;
            mask &= mask - 1;
            int s = __shfl_sync(0xffffffffu, myseg, p);
            float v0 = tile[l * 33 + p];            // bank (l+p)%32
            float v1 = tile[(l + 32) * 33 + p];
            acc[s * 64 + l]      += v0;             // bank l, exclusive
            acc[s * 64 + l + 32] += v1;
        }
    };

    // prologue: fill the 3-deep pipeline
    issue(cta,          0);
    issue(cta + 37,     1);
    issue(cta + 74,     2);

    int k = 0;
    for (int st = cta; st < 8192; st += 37, k++) {
        int buf = k % NBUF;
        asm volatile("cp.async.wait_group %0;" :: "n"(NBUF - 1) : "memory");
        __syncthreads();                    // tile[buf] fully resident
        accum(buf);
        __syncthreads();                    // everyone done reading buf
        issue(st + NBUF * 37, buf);         // refill (or empty commit)
    }
    asm volatile("cp.async.wait_group 0;" ::: "memory");
    __syncthreads();

    // ---- flush: TMA bulk-reduce the private accumulator into g_accum ----
    asm volatile("fence.proxy.async.shared::cta;" ::: "memory");
    if (l == 0) {
        float* dst = g_accum + ((size_t)(h * BB + b) * NT) * 64 + (size_t)w * 3200;
        uint32_t src = (uint32_t)__cvta_generic_to_shared(acc + w * 3200);
        asm volatile(
            "cp.reduce.async.bulk.global.shared::cta.bulk_group.add.f32 "
            "[%0], [%1], %2;"
            :: "l"(dst), "r"(src), "r"(12800) : "memory");
        asm volatile("cp.async.bulk.commit_group;" ::: "memory");
        asm volatile("cp.async.bulk.wait_group 0;" ::: "memory");
    }
}

// ---------------------------------------------------------------------------
// K4: finalize. Block per (b, sl): mean, mode, padding, pads.
// g_accum layout [h][b][sl][c] -> output position t = h*64+c (natural order).
// ---------------------------------------------------------------------------
__global__ __launch_bounds__(128) void k4_final(float* __restrict__ out) {
    int b  = blockIdx.y;
    int sl = blockIdx.x;
    int t  = threadIdx.x;

    float* tok = out + ((size_t)b * ML + sl) * CC;

    if (sl >= NT) {                       // padding region
        tok[t] = 0.f;
        if (t == 0) out[LAB_OFF + (size_t)b * ML + sl] = 0.f;
        return;
    }

    int s = b * NT + sl;

    __shared__ int s_cnt;
    if (t == 0) {
        int hh[NCLS], cnt = 0;
#pragma unroll
        for (int c = 0; c < NCLS; c++) { hh[c] = g_hist[s * NCLS + c]; cnt += hh[c]; }
        int best = 0, bc = hh[0];
#pragma unroll
        for (int c = 1; c < NCLS; c++) if (hh[c] > bc) { bc = hh[c]; best = c; }
        out[LAB_OFF + (size_t)b * ML + sl] = (float)best;
        if (sl == 0) out[PAD_OFF + b] = (float)(ML - NT);
        s_cnt = cnt;
    }
    __syncthreads();

    int cnt = s_cnt;
    float inv = 1.f / (float)(cnt > 0 ? cnt : 1);
    int hh = t >> 6, c = t & 63;
    float v = g_accum[(((size_t)(hh * BB + b) * NT) + sl) * 64 + c];
    tok[t] = v * inv;
}

// ---------------------------------------------------------------------------
extern "C" void kernel_launch(void* const* d_in, const int* in_sizes, int n_in,
                              void* d_out, int out_size) {
    const float* features = (const float*)d_in[0];
    const int*   gts      = (const int*)d_in[1];
    const int*   segments = (const int*)d_in[2];
    float*       out      = (float*)d_out;

    (void)in_sizes; (void)n_in; (void)out_size;

    static bool attr_set = false;
    if (!attr_set) {
        cudaFuncSetAttribute(k_pass, cudaFuncAttributeMaxDynamicSharedMemorySize,
                             SMEM_BYTES);
        attr_set = true;
    }

    k1_init<<<(NSEG * CC + 255) / 256, 256>>>();
    {
        dim3 g(37, BB, 2);                 // 296 CTAs = 2 waves
        k_pass<<<g, 512, SMEM_BYTES>>>(features, segments, gts);
    }
    {
        dim3 g(ML, BB);                    // (1024, 4)
        k4_final<<<g, 128>>>(out);
    }
}